// round 4
// baseline (speedup 1.0000x reference)
#include <cuda_runtime.h>
#include <math.h>
#include <stdint.h>

#define LSEQ 2048
#define DMODEL 2048
#define NH 32
#define NKV 8
#define HD 64
#define NB 2
#define WWIN 1024
#define KVD (NKV*HD)     // 512
#define MROWS (NB*LSEQ)  // 4096
#define PAD 36

// ---------------- scratch ----------------
static __device__ float g_q[(long long)MROWS * DMODEL];
static __device__ float g_k[(long long)MROWS * KVD];
static __device__ float g_v[(long long)MROWS * KVD];
static __device__ float g_ao[(long long)MROWS * DMODEL];
static __device__ float g_wqt[(long long)DMODEL * DMODEL];
static __device__ float g_wkt[(long long)KVD * DMODEL];
static __device__ float g_wvt[(long long)KVD * DMODEL];
static __device__ float g_wot[(long long)DMODEL * DMODEL];

__host__ __device__ __forceinline__ bool tile_dead(int i0, int j0) {
    return (j0 + 127 < i0) && (j0 >= i0 + 127 - WWIN);
}

__device__ __forceinline__ uint32_t f2tf(float f) {
    uint32_t u;
    asm("cvt.rna.tf32.f32 %0, %1;" : "=r"(u) : "f"(f));
    return u;
}
__device__ __forceinline__ uint4 cvt4(float4 v) {
    uint4 u; u.x = f2tf(v.x); u.y = f2tf(v.y); u.z = f2tf(v.z); u.w = f2tf(v.w); return u;
}
__device__ __forceinline__ void mma8(float* c, const uint32_t* a, const uint32_t* b) {
    asm volatile("mma.sync.aligned.m16n8k8.row.col.f32.tf32.tf32.f32 "
        "{%0,%1,%2,%3}, {%4,%5,%6,%7}, {%8,%9}, {%0,%1,%2,%3};"
        : "+f"(c[0]), "+f"(c[1]), "+f"(c[2]), "+f"(c[3])
        : "r"(a[0]), "r"(a[1]), "r"(a[2]), "r"(a[3]), "r"(b[0]), "r"(b[1]));
}

// ---------------- generic tf32 GEMM: C[M,N] = A[M,K] @ Bt[N,K]^T ----------------
__global__ __launch_bounds__(256) void tc_gemm(const float* __restrict__ A,
                                               const float* __restrict__ Bt,
                                               float* __restrict__ C,
                                               int M, int N, int K) {
    __shared__ uint32_t As[128 * PAD];
    __shared__ uint32_t Bs[128 * PAD];
    const int t = threadIdx.x, w = t >> 5, lane = t & 31, g = lane >> 2, tg = lane & 3;
    const int wm = w >> 2, wn = w & 3;
    const long long m0 = (long long)blockIdx.y * 128, n0 = (long long)blockIdx.x * 128;
    const int lr = t >> 1, lc = (t & 1) * 16;
    const float* ap = A + (m0 + lr) * (long long)K + lc;
    const float* bp = Bt + (n0 + lr) * (long long)K + lc;

    float4 pa[4], pb[4];
    #pragma unroll
    for (int i = 0; i < 4; i++) { pa[i] = *(const float4*)(ap + i * 4); pb[i] = *(const float4*)(bp + i * 4); }

    float acc[4][4][4] = {};
    const int nch = K / 32;
    for (int c = 0; c < nch; c++) {
        #pragma unroll
        for (int i = 0; i < 4; i++) {
            *(uint4*)&As[lr * PAD + lc + i * 4] = cvt4(pa[i]);
            *(uint4*)&Bs[lr * PAD + lc + i * 4] = cvt4(pb[i]);
        }
        __syncthreads();
        if (c + 1 < nch) {
            #pragma unroll
            for (int i = 0; i < 4; i++) {
                pa[i] = *(const float4*)(ap + (c + 1) * 32 + i * 4);
                pb[i] = *(const float4*)(bp + (c + 1) * 32 + i * 4);
            }
        }
        #pragma unroll
        for (int kk = 0; kk < 4; kk++) {
            const int k0 = kk * 8;
            uint32_t af[4][4], bf[4][2];
            #pragma unroll
            for (int fm = 0; fm < 4; fm++) {
                const int r = wm * 64 + fm * 16 + g;
                af[fm][0] = As[r * PAD + k0 + tg];       af[fm][1] = As[(r + 8) * PAD + k0 + tg];
                af[fm][2] = As[r * PAD + k0 + tg + 4];   af[fm][3] = As[(r + 8) * PAD + k0 + tg + 4];
            }
            #pragma unroll
            for (int fn = 0; fn < 4; fn++) {
                const int n = wn * 32 + fn * 8 + g;
                bf[fn][0] = Bs[n * PAD + k0 + tg];       bf[fn][1] = Bs[n * PAD + k0 + tg + 4];
            }
            #pragma unroll
            for (int fm = 0; fm < 4; fm++)
                #pragma unroll
                for (int fn = 0; fn < 4; fn++)
                    mma8(acc[fm][fn], af[fm], bf[fn]);
        }
        __syncthreads();
    }
    #pragma unroll
    for (int fm = 0; fm < 4; fm++) {
        const long long r0 = m0 + wm * 64 + fm * 16 + g;
        #pragma unroll
        for (int fn = 0; fn < 4; fn++) {
            const long long cc = n0 + wn * 32 + fn * 8 + 2 * tg;
            *(float2*)(C + r0 * N + cc)       = make_float2(acc[fm][fn][0], acc[fm][fn][1]);
            *(float2*)(C + (r0 + 8) * N + cc) = make_float2(acc[fm][fn][2], acc[fm][fn][3]);
        }
    }
}

// ---------------- fused flash attention: mask(QK^T/8) -> softmax -> @V ----------------
// Grid (16 i-tiles, 64 bh), 256 threads (8 warps), warp tile 16 rows x full width.
#define KSTR 68
#define VSTR 132
#define KS_OFF 0
#define VT_OFF (128*KSTR)               // 8704
#define PB_OFF (VT_OFF + 64*VSTR)       // 17152
#define SM_WORDS (PB_OFF + 8*16*PAD)    // 21760 words = 87040 B

__global__ __launch_bounds__(256) void flash_attn(const float* __restrict__ Q,
                                                  const float* __restrict__ Kg,
                                                  const float* __restrict__ Vg,
                                                  float* __restrict__ O) {
    extern __shared__ uint32_t sm[];
    uint32_t* KS = sm + KS_OFF;
    uint32_t* VT = sm + VT_OFF;
    const int bh = blockIdx.y, b = bh >> 5, h = bh & 31, kh = h >> 2;
    const int i0 = blockIdx.x * 128;
    const int t = threadIdx.x, w = t >> 5, lane = t & 31, g = lane >> 2, tg = lane & 3;
    uint32_t* PB = sm + PB_OFF + w * 16 * PAD;

    const int lr = t >> 1, lc = (t & 1) * 32;   // staging: 2 thr/row, 32 cols each

    // ---- stage Q tile into KS, pull fragments to registers ----
    {
        const float* qp = Q + ((long long)(b * LSEQ + i0 + lr)) * DMODEL + h * HD + lc;
        #pragma unroll
        for (int i = 0; i < 8; i++)
            *(uint4*)&KS[lr * KSTR + lc + i * 4] = cvt4(*(const float4*)(qp + i * 4));
    }
    __syncthreads();
    uint32_t qf[8][4];
    {
        const int r = w * 16 + g;
        #pragma unroll
        for (int ks = 0; ks < 8; ks++) {
            qf[ks][0] = KS[r * KSTR + ks * 8 + tg];
            qf[ks][1] = KS[(r + 8) * KSTR + ks * 8 + tg];
            qf[ks][2] = KS[r * KSTR + ks * 8 + tg + 4];
            qf[ks][3] = KS[(r + 8) * KSTR + ks * 8 + tg + 4];
        }
    }
    __syncthreads();

    float m[2] = {-3.0e38f, -3.0e38f}, l[2] = {0.0f, 0.0f};
    float oacc[8][4] = {};
    const int gi0 = i0 + w * 16 + g;

    for (int jt = 0; jt < 16; jt++) {
        const int j0 = jt << 7;
        if (tile_dead(i0, j0)) continue;

        // ---- load K tile (row-major) and V tile (transposed) ----
        {
            const float* kp = Kg + ((long long)(b * LSEQ + j0 + lr)) * KVD + kh * HD + lc;
            #pragma unroll
            for (int i = 0; i < 8; i++)
                *(uint4*)&KS[lr * KSTR + lc + i * 4] = cvt4(*(const float4*)(kp + i * 4));
            const float* vp = Vg + ((long long)(b * LSEQ + j0 + lr)) * KVD + kh * HD + lc;
            #pragma unroll
            for (int i = 0; i < 8; i++) {
                uint4 u = cvt4(*(const float4*)(vp + i * 4));
                const int d = lc + i * 4;
                VT[(d + 0) * VSTR + lr] = u.x;
                VT[(d + 1) * VSTR + lr] = u.y;
                VT[(d + 2) * VSTR + lr] = u.z;
                VT[(d + 3) * VSTR + lr] = u.w;
            }
        }
        __syncthreads();

        // ---- S = Q @ K^T (warp rows x 128 cols) ----
        float sacc[16][4] = {};
        #pragma unroll
        for (int ks = 0; ks < 8; ks++) {
            const int k0 = ks * 8;
            #pragma unroll
            for (int fn = 0; fn < 16; fn++) {
                uint32_t bf[2];
                const int n = fn * 8 + g;
                bf[0] = KS[n * KSTR + k0 + tg];
                bf[1] = KS[n * KSTR + k0 + tg + 4];
                mma8(sacc[fn], qf[ks], bf);
            }
        }

        // ---- mask, scale, online softmax ----
        #pragma unroll
        for (int rr = 0; rr < 2; rr++) {
            const int gi = gi0 + rr * 8;
            float mt = -3.0e38f;
            #pragma unroll
            for (int fn = 0; fn < 16; fn++) {
                #pragma unroll
                for (int e = 0; e < 2; e++) {
                    const int gj = j0 + fn * 8 + 2 * tg + e;
                    float v = sacc[fn][rr * 2 + e] * 0.125f;
                    if ((gj >= gi - WWIN) && (gj < gi)) v = -1e10f;
                    sacc[fn][rr * 2 + e] = v;
                    mt = fmaxf(mt, v);
                }
            }
            mt = fmaxf(mt, __shfl_xor_sync(0xffffffffu, mt, 1));
            mt = fmaxf(mt, __shfl_xor_sync(0xffffffffu, mt, 2));
            const float mn = fmaxf(m[rr], mt);
            const float sc = __expf(m[rr] - mn);
            float rs = 0.0f;
            #pragma unroll
            for (int fn = 0; fn < 16; fn++) {
                #pragma unroll
                for (int e = 0; e < 2; e++) {
                    float p = __expf(sacc[fn][rr * 2 + e] - mn);
                    sacc[fn][rr * 2 + e] = p;
                    rs += p;
                }
            }
            rs += __shfl_xor_sync(0xffffffffu, rs, 1);
            rs += __shfl_xor_sync(0xffffffffu, rs, 2);
            l[rr] = l[rr] * sc + rs;
            m[rr] = mn;
            #pragma unroll
            for (int fd = 0; fd < 8; fd++) {
                oacc[fd][rr * 2]     *= sc;
                oacc[fd][rr * 2 + 1] *= sc;
            }
        }

        // ---- O += P @ V, in 32-wide k chunks via per-warp smem relayout ----
        #pragma unroll
        for (int c4 = 0; c4 < 4; c4++) {
            #pragma unroll
            for (int f = 0; f < 4; f++) {
                const int fn = c4 * 4 + f;
                const int col = f * 8 + 2 * tg;
                uint2 u0 = make_uint2(f2tf(sacc[fn][0]), f2tf(sacc[fn][1]));
                uint2 u1 = make_uint2(f2tf(sacc[fn][2]), f2tf(sacc[fn][3]));
                *(uint2*)&PB[g * PAD + col]       = u0;
                *(uint2*)&PB[(g + 8) * PAD + col] = u1;
            }
            __syncwarp();
            #pragma unroll
            for (int ks2 = 0; ks2 < 4; ks2++) {
                uint32_t af[4];
                const int k0 = ks2 * 8;
                af[0] = PB[g * PAD + k0 + tg];
                af[1] = PB[(g + 8) * PAD + k0 + tg];
                af[2] = PB[g * PAD + k0 + tg + 4];
                af[3] = PB[(g + 8) * PAD + k0 + tg + 4];
                const int kj = c4 * 32 + k0;
                #pragma unroll
                for (int fd = 0; fd < 8; fd++) {
                    uint32_t bf[2];
                    const int n = fd * 8 + g;
                    bf[0] = VT[n * VSTR + kj + tg];
                    bf[1] = VT[n * VSTR + kj + tg + 4];
                    mma8(oacc[fd], af, bf);
                }
            }
            __syncwarp();
        }
        __syncthreads();
    }

    // ---- epilogue: divide by l, write O ----
    #pragma unroll
    for (int rr = 0; rr < 2; rr++) {
        const float inv = 1.0f / l[rr];
        float* orow = O + ((long long)(b * LSEQ + gi0 + rr * 8)) * DMODEL + h * HD;
        #pragma unroll
        for (int fd = 0; fd < 8; fd++) {
            *(float2*)(orow + fd * 8 + 2 * tg) =
                make_float2(oacc[fd][rr * 2] * inv, oacc[fd][rr * 2 + 1] * inv);
        }
    }
}

// ---------------- transpose ----------------
__global__ void transpose_k(const float* __restrict__ src, float* __restrict__ dst, int R, int C) {
    __shared__ float tb[32][33];
    const int c = blockIdx.x * 32, r = blockIdx.y * 32;
    const int tx = threadIdx.x, ty = threadIdx.y;
    #pragma unroll
    for (int i = 0; i < 32; i += 8) tb[ty + i][tx] = src[(long long)(r + ty + i) * C + c + tx];
    __syncthreads();
    #pragma unroll
    for (int i = 0; i < 32; i += 8) dst[(long long)(c + ty + i) * R + r + tx] = tb[tx][ty + i];
}

// ---------------- launch ----------------
extern "C" void kernel_launch(void* const* d_in, const int* in_sizes, int n_in,
                              void* d_out, int out_size) {
    const float* x  = (const float*)d_in[0];
    const float* wq = (const float*)d_in[1];
    const float* wk = (const float*)d_in[2];
    const float* wv = (const float*)d_in[3];
    const float* wo = (const float*)d_in[4];
    float* out = (float*)d_out;

    float *qb, *kb, *vb, *ab, *wqt, *wkt, *wvt, *wot;
    cudaGetSymbolAddress((void**)&qb, g_q);
    cudaGetSymbolAddress((void**)&kb, g_k);
    cudaGetSymbolAddress((void**)&vb, g_v);
    cudaGetSymbolAddress((void**)&ab, g_ao);
    cudaGetSymbolAddress((void**)&wqt, g_wqt);
    cudaGetSymbolAddress((void**)&wkt, g_wkt);
    cudaGetSymbolAddress((void**)&wvt, g_wvt);
    cudaGetSymbolAddress((void**)&wot, g_wot);

    cudaFuncSetAttribute(flash_attn, cudaFuncAttributeMaxDynamicSharedMemorySize, SM_WORDS * 4);

    dim3 tb32(32, 8);
    transpose_k<<<dim3(64, 64), tb32>>>(wq, wqt, DMODEL, DMODEL);
    transpose_k<<<dim3(16, 64), tb32>>>(wk, wkt, DMODEL, KVD);
    transpose_k<<<dim3(16, 64), tb32>>>(wv, wvt, DMODEL, KVD);
    transpose_k<<<dim3(64, 64), tb32>>>(wo, wot, DMODEL, DMODEL);

    tc_gemm<<<dim3(16, 32), 256>>>(x, wqt, qb, MROWS, DMODEL, DMODEL);
    tc_gemm<<<dim3(4, 32), 256>>>(x, wkt, kb, MROWS, KVD, DMODEL);
    tc_gemm<<<dim3(4, 32), 256>>>(x, wvt, vb, MROWS, KVD, DMODEL);

    flash_attn<<<dim3(16, 64), 256, SM_WORDS * 4>>>(qb, kb, vb, ab);

    tc_gemm<<<dim3(16, 32), 256>>>(ab, wot, out, MROWS, DMODEL, DMODEL);
}

// round 6
// speedup vs baseline: 1.2386x; 1.2386x over previous
#include <cuda_runtime.h>
#include <math.h>
#include <stdint.h>

#define LSEQ 2048
#define DMODEL 2048
#define NH 32
#define NKV 8
#define HD 64
#define NB 2
#define WWIN 1024
#define KVD (NKV*HD)     // 512
#define MROWS (NB*LSEQ)  // 4096
#define PAD 36

// ---------------- scratch ----------------
static __device__ float g_q[(long long)MROWS * DMODEL];
static __device__ float g_k[(long long)MROWS * KVD];
static __device__ float g_v[(long long)MROWS * KVD];
static __device__ float g_s[(long long)NB * NH * LSEQ * LSEQ];
static __device__ float g_ao[(long long)MROWS * DMODEL];
static __device__ float g_wqt[(long long)DMODEL * DMODEL];
static __device__ float g_wkt[(long long)KVD * DMODEL];
static __device__ float g_wvt[(long long)KVD * DMODEL];
static __device__ float g_wot[(long long)DMODEL * DMODEL];
static __device__ float g_vt[(long long)NB * NKV * HD * LSEQ];

__host__ __device__ __forceinline__ bool tile_dead(int i0, int j0) {
    return (j0 + 127 < i0) && (j0 >= i0 + 127 - WWIN);
}

__device__ __forceinline__ uint32_t f2tf(float f) {
    uint32_t u;
    asm("cvt.rna.tf32.f32 %0, %1;" : "=r"(u) : "f"(f));
    return u;
}
__device__ __forceinline__ uint4 cvt4(float4 v) {
    uint4 u; u.x = f2tf(v.x); u.y = f2tf(v.y); u.z = f2tf(v.z); u.w = f2tf(v.w); return u;
}
__device__ __forceinline__ void mma8(float* c, const uint32_t* a, const uint32_t* b) {
    asm volatile("mma.sync.aligned.m16n8k8.row.col.f32.tf32.tf32.f32 "
        "{%0,%1,%2,%3}, {%4,%5,%6,%7}, {%8,%9}, {%0,%1,%2,%3};"
        : "+f"(c[0]), "+f"(c[1]), "+f"(c[2]), "+f"(c[3])
        : "r"(a[0]), "r"(a[1]), "r"(a[2]), "r"(a[3]), "r"(b[0]), "r"(b[1]));
}

// ---------------- generic tf32 GEMM: C[M,N] = A[M,K] @ Bt[N,K]^T ----------------
__global__ __launch_bounds__(256) void tc_gemm(const float* __restrict__ A,
                                               const float* __restrict__ Bt,
                                               float* __restrict__ C,
                                               int M, int N, int K) {
    __shared__ uint32_t As[128 * PAD];
    __shared__ uint32_t Bs[128 * PAD];
    const int t = threadIdx.x, w = t >> 5, lane = t & 31, g = lane >> 2, tg = lane & 3;
    const int wm = w >> 2, wn = w & 3;
    const long long m0 = (long long)blockIdx.y * 128, n0 = (long long)blockIdx.x * 128;
    const int lr = t >> 1, lc = (t & 1) * 16;
    const float* ap = A + (m0 + lr) * (long long)K + lc;
    const float* bp = Bt + (n0 + lr) * (long long)K + lc;

    float4 pa[4], pb[4];
    #pragma unroll
    for (int i = 0; i < 4; i++) { pa[i] = *(const float4*)(ap + i * 4); pb[i] = *(const float4*)(bp + i * 4); }

    float acc[4][4][4] = {};
    const int nch = K / 32;
    for (int c = 0; c < nch; c++) {
        #pragma unroll
        for (int i = 0; i < 4; i++) {
            *(uint4*)&As[lr * PAD + lc + i * 4] = cvt4(pa[i]);
            *(uint4*)&Bs[lr * PAD + lc + i * 4] = cvt4(pb[i]);
        }
        __syncthreads();
        if (c + 1 < nch) {
            #pragma unroll
            for (int i = 0; i < 4; i++) {
                pa[i] = *(const float4*)(ap + (c + 1) * 32 + i * 4);
                pb[i] = *(const float4*)(bp + (c + 1) * 32 + i * 4);
            }
        }
        #pragma unroll
        for (int kk = 0; kk < 4; kk++) {
            const int k0 = kk * 8;
            uint32_t af[4][4], bf[4][2];
            #pragma unroll
            for (int fm = 0; fm < 4; fm++) {
                const int r = wm * 64 + fm * 16 + g;
                af[fm][0] = As[r * PAD + k0 + tg];       af[fm][1] = As[(r + 8) * PAD + k0 + tg];
                af[fm][2] = As[r * PAD + k0 + tg + 4];   af[fm][3] = As[(r + 8) * PAD + k0 + tg + 4];
            }
            #pragma unroll
            for (int fn = 0; fn < 4; fn++) {
                const int n = wn * 32 + fn * 8 + g;
                bf[fn][0] = Bs[n * PAD + k0 + tg];       bf[fn][1] = Bs[n * PAD + k0 + tg + 4];
            }
            #pragma unroll
            for (int fm = 0; fm < 4; fm++)
                #pragma unroll
                for (int fn = 0; fn < 4; fn++)
                    mma8(acc[fm][fn], af[fm], bf[fn]);
        }
        __syncthreads();
    }
    #pragma unroll
    for (int fm = 0; fm < 4; fm++) {
        const long long r0 = m0 + wm * 64 + fm * 16 + g;
        #pragma unroll
        for (int fn = 0; fn < 4; fn++) {
            const long long cc = n0 + wn * 32 + fn * 8 + 2 * tg;
            *(float2*)(C + r0 * N + cc)       = make_float2(acc[fm][fn][0], acc[fm][fn][1]);
            *(float2*)(C + (r0 + 8) * N + cc) = make_float2(acc[fm][fn][2], acc[fm][fn][3]);
        }
    }
}

// ---------------- scores: S = mask(QK^T / 8), skip dead tiles ----------------
__global__ __launch_bounds__(256) void tc_scores(const float* __restrict__ Q,
                                                 const float* __restrict__ Kb,
                                                 float* __restrict__ S) {
    const int bh = blockIdx.z, b = bh >> 5, h = bh & 31, kh = h >> 2;
    const int i0 = blockIdx.y * 128, j0 = blockIdx.x * 128;
    if (tile_dead(i0, j0)) return;
    __shared__ uint32_t As[128 * PAD];
    __shared__ uint32_t Bs[128 * PAD];
    const int t = threadIdx.x, w = t >> 5, lane = t & 31, g = lane >> 2, tg = lane & 3;
    const int wm = w >> 2, wn = w & 3;
    const int lr = t >> 1, lc = (t & 1) * 16;
    const float* qp = Q + ((long long)(b * LSEQ + i0 + lr)) * DMODEL + h * HD + lc;
    const float* kp = Kb + ((long long)(b * LSEQ + j0 + lr)) * KVD + kh * HD + lc;

    float acc[4][4][4] = {};
    for (int c = 0; c < 2; c++) {
        #pragma unroll
        for (int i = 0; i < 4; i++) {
            *(uint4*)&As[lr * PAD + lc + i * 4] = cvt4(*(const float4*)(qp + c * 32 + i * 4));
            *(uint4*)&Bs[lr * PAD + lc + i * 4] = cvt4(*(const float4*)(kp + c * 32 + i * 4));
        }
        __syncthreads();
        #pragma unroll
        for (int kk = 0; kk < 4; kk++) {
            const int k0 = kk * 8;
            uint32_t af[4][4], bf[4][2];
            #pragma unroll
            for (int fm = 0; fm < 4; fm++) {
                const int r = wm * 64 + fm * 16 + g;
                af[fm][0] = As[r * PAD + k0 + tg];       af[fm][1] = As[(r + 8) * PAD + k0 + tg];
                af[fm][2] = As[r * PAD + k0 + tg + 4];   af[fm][3] = As[(r + 8) * PAD + k0 + tg + 4];
            }
            #pragma unroll
            for (int fn = 0; fn < 4; fn++) {
                const int n = wn * 32 + fn * 8 + g;
                bf[fn][0] = Bs[n * PAD + k0 + tg];       bf[fn][1] = Bs[n * PAD + k0 + tg + 4];
            }
            #pragma unroll
            for (int fm = 0; fm < 4; fm++)
                #pragma unroll
                for (int fn = 0; fn < 4; fn++)
                    mma8(acc[fm][fn], af[fm], bf[fn]);
        }
        __syncthreads();
    }
    #pragma unroll
    for (int fm = 0; fm < 4; fm++) {
        #pragma unroll
        for (int rr = 0; rr < 2; rr++) {
            const int gi = i0 + wm * 64 + fm * 16 + g + rr * 8;
            float* srow = S + ((long long)bh * LSEQ + gi) * LSEQ;
            #pragma unroll
            for (int fn = 0; fn < 4; fn++) {
                const int gj = j0 + wn * 32 + fn * 8 + 2 * tg;
                const float v0 = acc[fm][fn][rr * 2], v1 = acc[fm][fn][rr * 2 + 1];
                const bool m0b = (gj >= gi - WWIN) && (gj < gi);
                const bool m1b = (gj + 1 >= gi - WWIN) && (gj + 1 < gi);
                *(float2*)(srow + gj) = make_float2(m0b ? -1e10f : v0 * 0.125f,
                                                    m1b ? -1e10f : v1 * 0.125f);
            }
        }
    }
}

// -------- fused PV + online softmax: O = softmax(S) @ V, streaming j-tiles --------
// Grid (16 i-tiles, 64 bh), 256 thr (8 warps, 4x2), warp tile 32x32 of O.
#define SPAD 132
#define SF_W  (128 * SPAD)             // S tile (float -> tf32 in place)
#define VS_W  (64 * SPAD)              // V^T tile [d][j]
#define SM_PVW (SF_W + VS_W + 256)     // + scrow[128] + lsm[128]

__global__ __launch_bounds__(256) void pv_fused(const float* __restrict__ S,
                                                const float* __restrict__ Vt,
                                                float* __restrict__ O) {
    extern __shared__ uint32_t sm[];
    uint32_t* Sfu = sm;
    float*    Sff = (float*)sm;
    uint32_t* Vsu = sm + SF_W;
    float*    scrow = (float*)(sm + SF_W + VS_W);
    float*    lsm   = scrow + 128;

    const int bh = blockIdx.y, b = bh >> 5, h = bh & 31, kh = h >> 2;
    const int i0 = blockIdx.x * 128;
    const int t = threadIdx.x, w = t >> 5, lane = t & 31, g = lane >> 2, tg = lane & 3;
    const int wm = w >> 1, wn = w & 1;
    const int lr = t >> 1, half = t & 1;          // S staging: 2 thr/row, 64 cols each

    const float* srow = S + ((long long)bh * LSEQ + i0 + lr) * LSEQ;
    const float* vbase = Vt + ((long long)(b * NKV + kh) * HD) * LSEQ;

    float mrow = -3.0e38f, lrow = 0.0f;           // duplicated across the row pair
    float acc[2][4][4] = {};

    for (int jt = 0; jt < 16; jt++) {
        const int j0 = jt << 7;
        if (tile_dead(i0, j0)) continue;

        // ---- stage S tile (float), track local max ----
        float tmax = -3.0e38f;
        {
            const float* sp = srow + j0 + half * 64;
            #pragma unroll
            for (int f = 0; f < 16; f++) {
                float4 v = *(const float4*)(sp + f * 4);
                tmax = fmaxf(tmax, fmaxf(fmaxf(v.x, v.y), fmaxf(v.z, v.w)));
                *(float4*)&Sff[lr * SPAD + half * 64 + f * 4] = v;
            }
        }
        // ---- stage V^T tile: Vs[d][j], ALL 64x128 elements ----
        {
            #pragma unroll
            for (int r = 0; r < 32; r++) {
                const int idx = t + r * 256;
                const int d = idx >> 7, j = idx & 127;
                Vsu[d * SPAD + j] = f2tf(vbase[(long long)d * LSEQ + j0 + j]);
            }
        }
        // ---- online softmax on this tile (row pair cooperates) ----
        tmax = fmaxf(tmax, __shfl_xor_sync(0xffffffffu, tmax, 1));
        const float mn = fmaxf(mrow, tmax);
        const float sc = __expf(mrow - mn);
        float rsum = 0.0f;
        #pragma unroll
        for (int f = 0; f < 16; f++) {
            float4 v = *(const float4*)&Sff[lr * SPAD + half * 64 + f * 4];
            float p0 = __expf(v.x - mn), p1 = __expf(v.y - mn);
            float p2 = __expf(v.z - mn), p3 = __expf(v.w - mn);
            rsum += (p0 + p1) + (p2 + p3);
            uint4 u; u.x = f2tf(p0); u.y = f2tf(p1); u.z = f2tf(p2); u.w = f2tf(p3);
            *(uint4*)&Sfu[lr * SPAD + half * 64 + f * 4] = u;
        }
        rsum += __shfl_xor_sync(0xffffffffu, rsum, 1);
        lrow = lrow * sc + rsum;
        mrow = mn;
        if (half == 0) scrow[lr] = sc;
        __syncthreads();

        // ---- rescale O accumulators by per-row exp(m_old - m_new) ----
        #pragma unroll
        for (int fm = 0; fm < 2; fm++) {
            const int r = wm * 32 + fm * 16 + g;
            const float s0 = scrow[r], s1 = scrow[r + 8];
            #pragma unroll
            for (int fn = 0; fn < 4; fn++) {
                acc[fm][fn][0] *= s0; acc[fm][fn][1] *= s0;
                acc[fm][fn][2] *= s1; acc[fm][fn][3] *= s1;
            }
        }
        // ---- O += P @ V over full 128-deep k ----
        #pragma unroll
        for (int ks = 0; ks < 16; ks++) {
            const int k0 = ks * 8;
            uint32_t af[2][4], bf[4][2];
            #pragma unroll
            for (int fm = 0; fm < 2; fm++) {
                const int r = wm * 32 + fm * 16 + g;
                af[fm][0] = Sfu[r * SPAD + k0 + tg];       af[fm][1] = Sfu[(r + 8) * SPAD + k0 + tg];
                af[fm][2] = Sfu[r * SPAD + k0 + tg + 4];   af[fm][3] = Sfu[(r + 8) * SPAD + k0 + tg + 4];
            }
            #pragma unroll
            for (int fn = 0; fn < 4; fn++) {
                const int n = wn * 32 + fn * 8 + g;
                bf[fn][0] = Vsu[n * SPAD + k0 + tg];       bf[fn][1] = Vsu[n * SPAD + k0 + tg + 4];
            }
            #pragma unroll
            for (int fm = 0; fm < 2; fm++)
                #pragma unroll
                for (int fn = 0; fn < 4; fn++)
                    mma8(acc[fm][fn], af[fm], bf[fn]);
        }
        __syncthreads();
    }

    // ---- epilogue: normalize by l, write O ----
    if (half == 0) lsm[lr] = lrow;
    __syncthreads();
    #pragma unroll
    for (int fm = 0; fm < 2; fm++) {
        const int r = wm * 32 + fm * 16 + g;
        const float inv0 = 1.0f / lsm[r], inv1 = 1.0f / lsm[r + 8];
        const long long r0 = i0 + r;
        #pragma unroll
        for (int fn = 0; fn < 4; fn++) {
            const int cc = h * HD + wn * 32 + fn * 8 + 2 * tg;
            float* cp0 = O + ((long long)(b * LSEQ) + r0) * DMODEL + cc;
            *(float2*)(cp0)                = make_float2(acc[fm][fn][0] * inv0, acc[fm][fn][1] * inv0);
            *(float2*)(cp0 + 8LL * DMODEL) = make_float2(acc[fm][fn][2] * inv1, acc[fm][fn][3] * inv1);
        }
    }
}

// ---------------- transposes ----------------
__global__ void transpose_k(const float* __restrict__ src, float* __restrict__ dst, int R, int C) {
    __shared__ float tb[32][33];
    const int c = blockIdx.x * 32, r = blockIdx.y * 32;
    const int tx = threadIdx.x, ty = threadIdx.y;
    #pragma unroll
    for (int i = 0; i < 32; i += 8) tb[ty + i][tx] = src[(long long)(r + ty + i) * C + c + tx];
    __syncthreads();
    #pragma unroll
    for (int i = 0; i < 32; i += 8) dst[(long long)(c + ty + i) * R + r + tx] = tb[tx][ty + i];
}
__global__ void vtrans_k(const float* __restrict__ V, float* __restrict__ Vt) {
    __shared__ float tb[32][33];
    const int bkh = blockIdx.z, b = bkh >> 3, kh = bkh & 7;
    const int j0 = blockIdx.x * 32, d0 = blockIdx.y * 32;
    const int tx = threadIdx.x, ty = threadIdx.y;
    #pragma unroll
    for (int i = 0; i < 32; i += 8)
        tb[ty + i][tx] = V[(long long)(b * LSEQ + j0 + ty + i) * KVD + kh * HD + d0 + tx];
    __syncthreads();
    #pragma unroll
    for (int i = 0; i < 32; i += 8)
        Vt[((long long)bkh * HD + d0 + ty + i) * LSEQ + j0 + tx] = tb[tx][ty + i];
}

// ---------------- launch ----------------
extern "C" void kernel_launch(void* const* d_in, const int* in_sizes, int n_in,
                              void* d_out, int out_size) {
    const float* x  = (const float*)d_in[0];
    const float* wq = (const float*)d_in[1];
    const float* wk = (const float*)d_in[2];
    const float* wv = (const float*)d_in[3];
    const float* wo = (const float*)d_in[4];
    float* out = (float*)d_out;

    float *qb, *kb, *vb, *sb, *ab, *wqt, *wkt, *wvt, *wot, *vt;
    cudaGetSymbolAddress((void**)&qb, g_q);
    cudaGetSymbolAddress((void**)&kb, g_k);
    cudaGetSymbolAddress((void**)&vb, g_v);
    cudaGetSymbolAddress((void**)&sb, g_s);
    cudaGetSymbolAddress((void**)&ab, g_ao);
    cudaGetSymbolAddress((void**)&wqt, g_wqt);
    cudaGetSymbolAddress((void**)&wkt, g_wkt);
    cudaGetSymbolAddress((void**)&wvt, g_wvt);
    cudaGetSymbolAddress((void**)&wot, g_wot);
    cudaGetSymbolAddress((void**)&vt, g_vt);

    cudaFuncSetAttribute(pv_fused, cudaFuncAttributeMaxDynamicSharedMemorySize, SM_PVW * 4);

    dim3 tb32(32, 8);
    transpose_k<<<dim3(64, 64), tb32>>>(wq, wqt, DMODEL, DMODEL);
    transpose_k<<<dim3(16, 64), tb32>>>(wk, wkt, DMODEL, KVD);
    transpose_k<<<dim3(16, 64), tb32>>>(wv, wvt, DMODEL, KVD);
    transpose_k<<<dim3(64, 64), tb32>>>(wo, wot, DMODEL, DMODEL);

    tc_gemm<<<dim3(16, 32), 256>>>(x, wqt, qb, MROWS, DMODEL, DMODEL);
    tc_gemm<<<dim3(4, 32), 256>>>(x, wkt, kb, MROWS, KVD, DMODEL);
    tc_gemm<<<dim3(4, 32), 256>>>(x, wvt, vb, MROWS, KVD, DMODEL);

    vtrans_k<<<dim3(64, 2, 16), tb32>>>(vb, vt);

    tc_scores<<<dim3(16, 16, NB * NH), 256>>>(qb, kb, sb);
    pv_fused<<<dim3(16, 64), 256, SM_PVW * 4>>>(sb, vt, ab);

    tc_gemm<<<dim3(16, 32), 256>>>(ab, wot, out, MROWS, DMODEL, DMODEL);
}

// round 7
// speedup vs baseline: 1.5079x; 1.2175x over previous
#include <cuda_runtime.h>
#include <math.h>
#include <stdint.h>

#define LSEQ 2048
#define DMODEL 2048
#define NH 32
#define NKV 8
#define HD 64
#define NB 2
#define WWIN 1024
#define KVD (NKV*HD)     // 512
#define MROWS (NB*LSEQ)  // 4096
#define PAD 36
#define SPAD 132

// ---------------- scratch ----------------
static __device__ float g_q[(long long)MROWS * DMODEL];
static __device__ float g_k[(long long)MROWS * KVD];
static __device__ float g_v[(long long)MROWS * KVD];
static __device__ float g_ao[(long long)MROWS * DMODEL];
static __device__ float g_wqt[(long long)DMODEL * DMODEL];
static __device__ float g_wkt[(long long)KVD * DMODEL];
static __device__ float g_wvt[(long long)KVD * DMODEL];
static __device__ float g_wot[(long long)DMODEL * DMODEL];
static __device__ float g_vt[(long long)NB * NKV * HD * LSEQ];

__host__ __device__ __forceinline__ bool tile_dead(int i0, int j0) {
    return (j0 + 127 < i0) && (j0 >= i0 + 127 - WWIN);
}

__device__ __forceinline__ uint32_t f2tf(float f) {
    uint32_t u;
    asm("cvt.rna.tf32.f32 %0, %1;" : "=r"(u) : "f"(f));
    return u;
}
__device__ __forceinline__ uint4 cvt4(float4 v) {
    uint4 u; u.x = f2tf(v.x); u.y = f2tf(v.y); u.z = f2tf(v.z); u.w = f2tf(v.w); return u;
}
__device__ __forceinline__ void mma8(float* c, const uint32_t* a, const uint32_t* b) {
    asm volatile("mma.sync.aligned.m16n8k8.row.col.f32.tf32.tf32.f32 "
        "{%0,%1,%2,%3}, {%4,%5,%6,%7}, {%8,%9}, {%0,%1,%2,%3};"
        : "+f"(c[0]), "+f"(c[1]), "+f"(c[2]), "+f"(c[3])
        : "r"(a[0]), "r"(a[1]), "r"(a[2]), "r"(a[3]), "r"(b[0]), "r"(b[1]));
}

// ------- tf32 GEMM, double-buffered: C[M,N] = A[M,K] @ Bt[N,K]^T -------
// CTA tile 128x128, 256 thr, warp tile 64x32, K-chunk 32, ONE sync per chunk.
#define GBUF 9216   // words per buffer (As 4608 + Bs 4608)
__global__ __launch_bounds__(256) void tc_gemm(const float* __restrict__ A,
                                               const float* __restrict__ Bt,
                                               float* __restrict__ C,
                                               int M, int N, int K) {
    extern __shared__ uint32_t gsm[];
    const int t = threadIdx.x, w = t >> 5, lane = t & 31, g = lane >> 2, tg = lane & 3;
    const int wm = w >> 2, wn = w & 3;
    const long long m0 = (long long)blockIdx.y * 128, n0 = (long long)blockIdx.x * 128;
    const int lr = t >> 1, lc = (t & 1) * 16;
    const float* ap = A + (m0 + lr) * (long long)K + lc;
    const float* bp = Bt + (n0 + lr) * (long long)K + lc;

    float4 pa[4], pb[4];
    #pragma unroll
    for (int i = 0; i < 4; i++) { pa[i] = *(const float4*)(ap + i * 4); pb[i] = *(const float4*)(bp + i * 4); }
    {
        uint32_t* As = gsm; uint32_t* Bs = gsm + 4608;
        #pragma unroll
        for (int i = 0; i < 4; i++) {
            *(uint4*)&As[lr * PAD + lc + i * 4] = cvt4(pa[i]);
            *(uint4*)&Bs[lr * PAD + lc + i * 4] = cvt4(pb[i]);
        }
    }
    __syncthreads();

    float acc[4][4][4] = {};
    const int nch = K / 32;
    for (int c = 0; c < nch; c++) {
        uint32_t* As = gsm + (c & 1) * GBUF;
        uint32_t* Bs = As + 4608;
        if (c + 1 < nch) {
            #pragma unroll
            for (int i = 0; i < 4; i++) {
                pa[i] = *(const float4*)(ap + (c + 1) * 32 + i * 4);
                pb[i] = *(const float4*)(bp + (c + 1) * 32 + i * 4);
            }
        }
        #pragma unroll
        for (int kk = 0; kk < 4; kk++) {
            const int k0 = kk * 8;
            uint32_t af[4][4], bf[4][2];
            #pragma unroll
            for (int fm = 0; fm < 4; fm++) {
                const int r = wm * 64 + fm * 16 + g;
                af[fm][0] = As[r * PAD + k0 + tg];       af[fm][1] = As[(r + 8) * PAD + k0 + tg];
                af[fm][2] = As[r * PAD + k0 + tg + 4];   af[fm][3] = As[(r + 8) * PAD + k0 + tg + 4];
            }
            #pragma unroll
            for (int fn = 0; fn < 4; fn++) {
                const int n = wn * 32 + fn * 8 + g;
                bf[fn][0] = Bs[n * PAD + k0 + tg];       bf[fn][1] = Bs[n * PAD + k0 + tg + 4];
            }
            #pragma unroll
            for (int fm = 0; fm < 4; fm++)
                #pragma unroll
                for (int fn = 0; fn < 4; fn++)
                    mma8(acc[fm][fn], af[fm], bf[fn]);
        }
        if (c + 1 < nch) {
            uint32_t* An = gsm + ((c + 1) & 1) * GBUF;
            uint32_t* Bn = An + 4608;
            #pragma unroll
            for (int i = 0; i < 4; i++) {
                *(uint4*)&An[lr * PAD + lc + i * 4] = cvt4(pa[i]);
                *(uint4*)&Bn[lr * PAD + lc + i * 4] = cvt4(pb[i]);
            }
        }
        __syncthreads();
    }
    #pragma unroll
    for (int fm = 0; fm < 4; fm++) {
        const long long r0 = m0 + wm * 64 + fm * 16 + g;
        #pragma unroll
        for (int fn = 0; fn < 4; fn++) {
            const long long cc = n0 + wn * 32 + fn * 8 + 2 * tg;
            *(float2*)(C + r0 * N + cc)       = make_float2(acc[fm][fn][0], acc[fm][fn][1]);
            *(float2*)(C + (r0 + 8) * N + cc) = make_float2(acc[fm][fn][2], acc[fm][fn][3]);
        }
    }
}

// -------- fully fused attention: S=mask(QK^T/8) -> online softmax -> @V --------
// Grid (16 i-tiles, 64 bh), 256 thr (8 warps).
// S phase: warp grid 4x2 (32 rows x 64 cols). PV phase: warp grid 4x2 (32x32 of O).
#define QS_OFF 0
#define KS_OFF 8704
#define VS_OFF 17408
#define SFU_OFF 25856
#define MROW_OFF 42752
#define LROW_OFF 42880
#define SCROW_OFF 43008
#define PMAX_OFF 43136
#define PSUM_OFF 43392
#define ATT_SMW 43648

__global__ __launch_bounds__(256) void attn_fused(const float* __restrict__ Q,
                                                  const float* __restrict__ Kg,
                                                  const float* __restrict__ Vt,
                                                  float* __restrict__ O) {
    extern __shared__ uint32_t sm[];
    uint32_t* QS  = sm + QS_OFF;
    uint32_t* KS  = sm + KS_OFF;
    uint32_t* VS  = sm + VS_OFF;
    uint32_t* SFU = sm + SFU_OFF;
    float* mrow  = (float*)(sm + MROW_OFF);
    float* lrow  = (float*)(sm + LROW_OFF);
    float* scrow = (float*)(sm + SCROW_OFF);
    float* pmax  = (float*)(sm + PMAX_OFF);
    float* psum  = (float*)(sm + PSUM_OFF);

    const int bh = blockIdx.y, b = bh >> 5, h = bh & 31, kh = h >> 2;
    const int i0 = blockIdx.x * 128;
    const int t = threadIdx.x, w = t >> 5, lane = t & 31, g = lane >> 2, tg = lane & 3;
    const int wm = w >> 1, wn = w & 1;
    const int lr = t >> 1, half = t & 1;

    if (t < 128) { mrow[t] = -3.0e38f; lrow[t] = 0.0f; }

    {   // stage Q tile (128 x 64), tf32
        const float* qp = Q + ((long long)(b * LSEQ + i0 + lr)) * DMODEL + h * HD + half * 32;
        #pragma unroll
        for (int f = 0; f < 8; f++)
            *(uint4*)&QS[lr * 68 + half * 32 + f * 4] = cvt4(*(const float4*)(qp + f * 4));
    }
    const float* vbase = Vt + ((long long)(b * NKV + kh) * HD) * LSEQ;
    __syncthreads();

    float oacc[2][4][4] = {};

    for (int jt = 0; jt < 16; jt++) {
        const int j0 = jt << 7;
        if (tile_dead(i0, j0)) continue;

        {   // stage K tile (128 x 64)
            const float* kp = Kg + ((long long)(b * LSEQ + j0 + lr)) * KVD + kh * HD + half * 32;
            #pragma unroll
            for (int f = 0; f < 8; f++)
                *(uint4*)&KS[lr * 68 + half * 32 + f * 4] = cvt4(*(const float4*)(kp + f * 4));
            // stage V^T tile (64 x 128)
            #pragma unroll
            for (int r = 0; r < 32; r++) {
                const int idx = t + r * 256;
                const int d = idx >> 7, j = idx & 127;
                VS[d * SPAD + j] = f2tf(vbase[(long long)d * LSEQ + j0 + j]);
            }
        }
        __syncthreads();

        // ---- S = Q @ K^T : warp tile 32 rows x 64 cols ----
        float sacc[2][8][4] = {};
        #pragma unroll
        for (int ks = 0; ks < 8; ks++) {
            const int k0 = ks * 8;
            uint32_t af[2][4], bf[8][2];
            #pragma unroll
            for (int fm = 0; fm < 2; fm++) {
                const int r = wm * 32 + fm * 16 + g;
                af[fm][0] = QS[r * 68 + k0 + tg];       af[fm][1] = QS[(r + 8) * 68 + k0 + tg];
                af[fm][2] = QS[r * 68 + k0 + tg + 4];   af[fm][3] = QS[(r + 8) * 68 + k0 + tg + 4];
            }
            #pragma unroll
            for (int fn = 0; fn < 8; fn++) {
                const int n = wn * 64 + fn * 8 + g;
                bf[fn][0] = KS[n * 68 + k0 + tg];       bf[fn][1] = KS[n * 68 + k0 + tg + 4];
            }
            #pragma unroll
            for (int fm = 0; fm < 2; fm++)
                #pragma unroll
                for (int fn = 0; fn < 8; fn++)
                    mma8(sacc[fm][fn], af[fm], bf[fn]);
        }

        // ---- mask + scale + per-row tile max (quad-local, then cross-warp smem) ----
        #pragma unroll
        for (int fm = 0; fm < 2; fm++) {
            const int gi0v = i0 + wm * 32 + fm * 16 + g, gi1v = gi0v + 8;
            float mx0 = -3.0e38f, mx1 = -3.0e38f;
            #pragma unroll
            for (int fn = 0; fn < 8; fn++) {
                #pragma unroll
                for (int e = 0; e < 2; e++) {
                    const int gj = j0 + wn * 64 + fn * 8 + 2 * tg + e;
                    float v0 = sacc[fm][fn][e] * 0.125f;
                    if (gj >= gi0v - WWIN && gj < gi0v) v0 = -1e10f;
                    sacc[fm][fn][e] = v0; mx0 = fmaxf(mx0, v0);
                    float v1 = sacc[fm][fn][2 + e] * 0.125f;
                    if (gj >= gi1v - WWIN && gj < gi1v) v1 = -1e10f;
                    sacc[fm][fn][2 + e] = v1; mx1 = fmaxf(mx1, v1);
                }
            }
            mx0 = fmaxf(mx0, __shfl_xor_sync(0xffffffffu, mx0, 1));
            mx0 = fmaxf(mx0, __shfl_xor_sync(0xffffffffu, mx0, 2));
            mx1 = fmaxf(mx1, __shfl_xor_sync(0xffffffffu, mx1, 1));
            mx1 = fmaxf(mx1, __shfl_xor_sync(0xffffffffu, mx1, 2));
            if (tg == 0) {
                pmax[wn * 128 + wm * 32 + fm * 16 + g]     = mx0;
                pmax[wn * 128 + wm * 32 + fm * 16 + g + 8] = mx1;
            }
        }
        __syncthreads();
        if (t < 128) {
            const float mn = fmaxf(mrow[t], fmaxf(pmax[t], pmax[128 + t]));
            scrow[t] = __expf(mrow[t] - mn);
            mrow[t] = mn;
        }
        __syncthreads();

        // ---- exp, write tf32 P to SFU, partial sums; rescale oacc ----
        #pragma unroll
        for (int fm = 0; fm < 2; fm++) {
            const int r0 = wm * 32 + fm * 16 + g, r1 = r0 + 8;
            const float mn0 = mrow[r0], mn1 = mrow[r1];
            float rs0 = 0.0f, rs1 = 0.0f;
            #pragma unroll
            for (int fn = 0; fn < 8; fn++) {
                const int col = wn * 64 + fn * 8 + 2 * tg;
                const float p0 = __expf(sacc[fm][fn][0] - mn0), p1 = __expf(sacc[fm][fn][1] - mn0);
                const float p2 = __expf(sacc[fm][fn][2] - mn1), p3 = __expf(sacc[fm][fn][3] - mn1);
                rs0 += p0 + p1; rs1 += p2 + p3;
                SFU[r0 * SPAD + col] = f2tf(p0); SFU[r0 * SPAD + col + 1] = f2tf(p1);
                SFU[r1 * SPAD + col] = f2tf(p2); SFU[r1 * SPAD + col + 1] = f2tf(p3);
            }
            rs0 += __shfl_xor_sync(0xffffffffu, rs0, 1);
            rs0 += __shfl_xor_sync(0xffffffffu, rs0, 2);
            rs1 += __shfl_xor_sync(0xffffffffu, rs1, 1);
            rs1 += __shfl_xor_sync(0xffffffffu, rs1, 2);
            if (tg == 0) { psum[wn * 128 + r0] = rs0; psum[wn * 128 + r1] = rs1; }
            const float s0 = scrow[r0], s1 = scrow[r1];
            #pragma unroll
            for (int fn = 0; fn < 4; fn++) {
                oacc[fm][fn][0] *= s0; oacc[fm][fn][1] *= s0;
                oacc[fm][fn][2] *= s1; oacc[fm][fn][3] *= s1;
            }
        }
        __syncthreads();
        if (t < 128) lrow[t] = lrow[t] * scrow[t] + psum[t] + psum[128 + t];

        // ---- O += P @ V : warp tile 32 rows x 32 cols, k = 128 ----
        #pragma unroll
        for (int ks = 0; ks < 16; ks++) {
            const int k0 = ks * 8;
            uint32_t af[2][4], bf[4][2];
            #pragma unroll
            for (int fm = 0; fm < 2; fm++) {
                const int r = wm * 32 + fm * 16 + g;
                af[fm][0] = SFU[r * SPAD + k0 + tg];       af[fm][1] = SFU[(r + 8) * SPAD + k0 + tg];
                af[fm][2] = SFU[r * SPAD + k0 + tg + 4];   af[fm][3] = SFU[(r + 8) * SPAD + k0 + tg + 4];
            }
            #pragma unroll
            for (int fn = 0; fn < 4; fn++) {
                const int n = wn * 32 + fn * 8 + g;
                bf[fn][0] = VS[n * SPAD + k0 + tg];        bf[fn][1] = VS[n * SPAD + k0 + tg + 4];
            }
            #pragma unroll
            for (int fm = 0; fm < 2; fm++)
                #pragma unroll
                for (int fn = 0; fn < 4; fn++)
                    mma8(oacc[fm][fn], af[fm], bf[fn]);
        }
        __syncthreads();
    }

    // ---- epilogue: normalize by l, write O ----
    #pragma unroll
    for (int fm = 0; fm < 2; fm++) {
        const int r = wm * 32 + fm * 16 + g;
        const float inv0 = 1.0f / lrow[r], inv1 = 1.0f / lrow[r + 8];
        const long long r0 = i0 + r;
        #pragma unroll
        for (int fn = 0; fn < 4; fn++) {
            const int cc = h * HD + wn * 32 + fn * 8 + 2 * tg;
            float* cp0 = O + ((long long)(b * LSEQ) + r0) * DMODEL + cc;
            *(float2*)(cp0)                = make_float2(oacc[fm][fn][0] * inv0, oacc[fm][fn][1] * inv0);
            *(float2*)(cp0 + 8LL * DMODEL) = make_float2(oacc[fm][fn][2] * inv1, oacc[fm][fn][3] * inv1);
        }
    }
}

// ---------------- transposes ----------------
__global__ void transpose_k(const float* __restrict__ src, float* __restrict__ dst, int R, int C) {
    __shared__ float tb[32][33];
    const int c = blockIdx.x * 32, r = blockIdx.y * 32;
    const int tx = threadIdx.x, ty = threadIdx.y;
    #pragma unroll
    for (int i = 0; i < 32; i += 8) tb[ty + i][tx] = src[(long long)(r + ty + i) * C + c + tx];
    __syncthreads();
    #pragma unroll
    for (int i = 0; i < 32; i += 8) dst[(long long)(c + ty + i) * R + r + tx] = tb[tx][ty + i];
}
__global__ void vtrans_k(const float* __restrict__ V, float* __restrict__ Vt) {
    __shared__ float tb[32][33];
    const int bkh = blockIdx.z, b = bkh >> 3, kh = bkh & 7;
    const int j0 = blockIdx.x * 32, d0 = blockIdx.y * 32;
    const int tx = threadIdx.x, ty = threadIdx.y;
    #pragma unroll
    for (int i = 0; i < 32; i += 8)
        tb[ty + i][tx] = V[(long long)(b * LSEQ + j0 + ty + i) * KVD + kh * HD + d0 + tx];
    __syncthreads();
    #pragma unroll
    for (int i = 0; i < 32; i += 8)
        Vt[((long long)bkh * HD + d0 + ty + i) * LSEQ + j0 + tx] = tb[tx][ty + i];
}

// ---------------- launch ----------------
extern "C" void kernel_launch(void* const* d_in, const int* in_sizes, int n_in,
                              void* d_out, int out_size) {
    const float* x  = (const float*)d_in[0];
    const float* wq = (const float*)d_in[1];
    const float* wk = (const float*)d_in[2];
    const float* wv = (const float*)d_in[3];
    const float* wo = (const float*)d_in[4];
    float* out = (float*)d_out;

    float *qb, *kb, *vb, *ab, *wqt, *wkt, *wvt, *wot, *vt;
    cudaGetSymbolAddress((void**)&qb, g_q);
    cudaGetSymbolAddress((void**)&kb, g_k);
    cudaGetSymbolAddress((void**)&vb, g_v);
    cudaGetSymbolAddress((void**)&ab, g_ao);
    cudaGetSymbolAddress((void**)&wqt, g_wqt);
    cudaGetSymbolAddress((void**)&wkt, g_wkt);
    cudaGetSymbolAddress((void**)&wvt, g_wvt);
    cudaGetSymbolAddress((void**)&wot, g_wot);
    cudaGetSymbolAddress((void**)&vt, g_vt);

    const int GEMM_SM = 2 * GBUF * 4;       // 73728 B
    const int ATT_SM  = ATT_SMW * 4;        // 174592 B
    cudaFuncSetAttribute(tc_gemm,    cudaFuncAttributeMaxDynamicSharedMemorySize, GEMM_SM);
    cudaFuncSetAttribute(attn_fused, cudaFuncAttributeMaxDynamicSharedMemorySize, ATT_SM);

    dim3 tb32(32, 8);
    transpose_k<<<dim3(64, 64), tb32>>>(wq, wqt, DMODEL, DMODEL);
    transpose_k<<<dim3(16, 64), tb32>>>(wk, wkt, DMODEL, KVD);
    transpose_k<<<dim3(16, 64), tb32>>>(wv, wvt, DMODEL, KVD);
    transpose_k<<<dim3(64, 64), tb32>>>(wo, wot, DMODEL, DMODEL);

    tc_gemm<<<dim3(16, 32), 256, GEMM_SM>>>(x, wqt, qb, MROWS, DMODEL, DMODEL);
    tc_gemm<<<dim3(4, 32), 256, GEMM_SM>>>(x, wkt, kb, MROWS, KVD, DMODEL);
    tc_gemm<<<dim3(4, 32), 256, GEMM_SM>>>(x, wvt, vb, MROWS, KVD, DMODEL);

    vtrans_k<<<dim3(64, 2, 16), tb32>>>(vb, vt);

    attn_fused<<<dim3(16, 64), 256, ATT_SM>>>(qb, kb, vt, ab);

    tc_gemm<<<dim3(16, 32), 256, GEMM_SM>>>(ab, wot, out, MROWS, DMODEL, DMODEL);
}